// round 4
// baseline (speedup 1.0000x reference)
#include <cuda_runtime.h>
#include <cuda_bf16.h>
#include <math.h>

#define NMAX 50000
#define DDIM 256

// ---------------- scratch (no allocations allowed) ----------------
__device__ float g_x[NMAX * DDIM];     // current node features
__device__ float g_m[NMAX * DDIM];     // message accumulator
__device__ float g_ns[NMAX];           // out-degree norm (src side)
__device__ float g_nd[NMAX];           // in-degree norm (dst side)
__device__ float g_sum[DDIM];
__device__ float g_sumsq[DDIM];

// ---------------- small utility kernels ----------------
__global__ void zero_kernel(float* __restrict__ p, int n4) {
    int i = blockIdx.x * blockDim.x + threadIdx.x;
    if (i < n4) reinterpret_cast<float4*>(p)[i] = make_float4(0.f, 0.f, 0.f, 0.f);
}

__global__ void degree_kernel(const int* __restrict__ src, const int* __restrict__ dst,
                              float* __restrict__ ns, float* __restrict__ nd, int E) {
    int e = blockIdx.x * blockDim.x + threadIdx.x;
    if (e < E) {
        atomicAdd(&ns[src[e]], 1.f);
        atomicAdd(&nd[dst[e]], 1.f);
    }
}

__global__ void norm_fin_kernel(float* __restrict__ ns, float* __restrict__ nd, int n) {
    int i = blockIdx.x * blockDim.x + threadIdx.x;
    if (i < n) {
        ns[i] = rsqrtf(fmaxf(ns[i], 1.f));
        nd[i] = rsqrtf(fmaxf(nd[i], 1.f));
    }
}

// One warp per edge: m[dst] += x[src] * norm_s[src]  (256 floats, 8 per lane)
__global__ void scatter_kernel(const float* __restrict__ x, const float* __restrict__ ns,
                               const int* __restrict__ src, const int* __restrict__ dst,
                               float* __restrict__ m, int E) {
    int gw = (blockIdx.x * blockDim.x + threadIdx.x) >> 5;
    int lane = threadIdx.x & 31;
    if (gw >= E) return;
    int s = src[gw];
    int d = dst[gw];
    float sc = ns[s];
    const float* xs = x + (size_t)s * DDIM;
    float* md = m + (size_t)d * DDIM;
    // Front-batch the 8 gathers for MLP before issuing atomics.
    float v[DDIM / 32];
#pragma unroll
    for (int j = 0; j < DDIM / 32; j++) v[j] = xs[lane + j * 32];
#pragma unroll
    for (int j = 0; j < DDIM / 32; j++) {
        atomicAdd(md + lane + j * 32, v[j] * sc);
    }
}

// Column stats: blockDim.x == DDIM, each thread owns one column, rows strided by grid.
__global__ void bn_stats_kernel(const float* __restrict__ x, float* __restrict__ sum,
                                float* __restrict__ sumsq, int rows) {
    int col = threadIdx.x;
    float s = 0.f, s2 = 0.f;
    for (int r = blockIdx.x; r < rows; r += gridDim.x) {
        float v = x[(size_t)r * DDIM + col];
        s += v;
        s2 += v * v;
    }
    atomicAdd(&sum[col], s);
    atomicAdd(&sumsq[col], s2);
}

__global__ void bn_elu_kernel(float* __restrict__ x, const float* __restrict__ sum,
                              const float* __restrict__ sumsq, const float* __restrict__ gamma,
                              const float* __restrict__ beta, int rows) {
    int idx = blockIdx.x * blockDim.x + threadIdx.x;
    int total = rows * DDIM;
    if (idx >= total) return;
    int col = idx & (DDIM - 1);
    float inv_n = 1.f / (float)rows;
    float mu = sum[col] * inv_n;
    float var = sumsq[col] * inv_n - mu * mu;
    float y = gamma[col] * (x[idx] - mu) * rsqrtf(var + 1e-5f) + beta[col];
    x[idx] = (y > 0.f) ? y : expm1f(y);
}

// ---------------- fp32 tiled GEMM: C[M,N] = (A[M,K] * rowscale?) @ B[K,N] + bias ----------------
// BM=64, BN=64, BK=16, 256 threads, 4x4 micro-tile per thread.
template <bool SCALE_A>
__global__ __launch_bounds__(256) void gemm_kernel(
    const float* __restrict__ A, const float* __restrict__ rowscale,
    const float* __restrict__ B, const float* __restrict__ bias,
    float* __restrict__ C, int M, int N, int K) {
    __shared__ float As[16][68];  // [k][row], padded
    __shared__ float Bs[16][64];  // [k][col]

    int tid = threadIdx.x;
    int tx = tid & 15;          // col group
    int ty = tid >> 4;          // row group
    int row0 = blockIdx.y * 64;
    int col0 = blockIdx.x * 64;

    // A tile loader: thread -> (arow, ak4)
    int arow = tid >> 2;
    int ak4 = (tid & 3) * 4;
    // B tile loader: thread -> (brow, bc4)
    int brow = tid >> 4;
    int bc4 = (tid & 15) * 4;

    float ascale = 1.f;
    if (SCALE_A) {
        if (row0 + arow < M) ascale = rowscale[row0 + arow];
    }

    float acc[4][4];
#pragma unroll
    for (int i = 0; i < 4; i++)
#pragma unroll
        for (int j = 0; j < 4; j++) acc[i][j] = 0.f;

    for (int k0 = 0; k0 < K; k0 += 16) {
        float4 a = make_float4(0.f, 0.f, 0.f, 0.f);
        if (row0 + arow < M)
            a = *reinterpret_cast<const float4*>(A + (size_t)(row0 + arow) * K + k0 + ak4);
        if (SCALE_A) { a.x *= ascale; a.y *= ascale; a.z *= ascale; a.w *= ascale; }
        As[ak4 + 0][arow] = a.x;
        As[ak4 + 1][arow] = a.y;
        As[ak4 + 2][arow] = a.z;
        As[ak4 + 3][arow] = a.w;

        float4 b = make_float4(0.f, 0.f, 0.f, 0.f);
        if (col0 + bc4 < N)
            b = *reinterpret_cast<const float4*>(B + (size_t)(k0 + brow) * N + col0 + bc4);
        *reinterpret_cast<float4*>(&Bs[brow][bc4]) = b;

        __syncthreads();
#pragma unroll
        for (int kk = 0; kk < 16; kk++) {
            float4 ra = *reinterpret_cast<const float4*>(&As[kk][ty * 4]);
            float4 rb = *reinterpret_cast<const float4*>(&Bs[kk][tx * 4]);
            float av[4] = {ra.x, ra.y, ra.z, ra.w};
            float bv[4] = {rb.x, rb.y, rb.z, rb.w};
#pragma unroll
            for (int i = 0; i < 4; i++)
#pragma unroll
                for (int j = 0; j < 4; j++) acc[i][j] += av[i] * bv[j];
        }
        __syncthreads();
    }

    int c0 = col0 + tx * 4;
    if (c0 < N) {  // N is a multiple of 4 in all uses
        float4 bv = *reinterpret_cast<const float4*>(bias + c0);
#pragma unroll
        for (int i = 0; i < 4; i++) {
            int r = row0 + ty * 4 + i;
            if (r < M) {
                float4 o;
                o.x = acc[i][0] + bv.x;
                o.y = acc[i][1] + bv.y;
                o.z = acc[i][2] + bv.z;
                o.w = acc[i][3] + bv.w;
                *reinterpret_cast<float4*>(C + (size_t)r * N + c0) = o;
            }
        }
    }
}

// ---------------- host orchestration ----------------
static inline dim3 gemm_grid(int M, int N) { return dim3((N + 63) / 64, (M + 63) / 64); }

extern "C" void kernel_launch(void* const* d_in, const int* in_sizes, int n_in,
                              void* d_out, int out_size) {
    const float* feat  = (const float*)d_in[0];
    const int*   src   = (const int*)d_in[1];
    const int*   dst   = (const int*)d_in[2];
    const float* W_fc  = (const float*)d_in[3];
    const float* b_fc  = (const float*)d_in[4];
    const float* W1    = (const float*)d_in[5];
    const float* b1    = (const float*)d_in[6];
    const float* W2    = (const float*)d_in[7];
    const float* b2    = (const float*)d_in[8];
    const float* W3    = (const float*)d_in[9];
    const float* b3    = (const float*)d_in[10];
    const float* gamma = (const float*)d_in[11];
    const float* beta  = (const float*)d_in[12];
    const float* W_lin = (const float*)d_in[13];
    const float* b_lin = (const float*)d_in[14];

    const int F = 1024;
    const int Nn = in_sizes[0] / F;          // 50000
    const int E = in_sizes[1];               // 300000
    const int C = in_sizes[13] / DDIM;       // 40

    float* out_x = (float*)d_out;
    float* out_logits = out_x + (size_t)Nn * DDIM;

    float *px, *pm, *pns, *pnd, *psum, *psumsq;
    cudaGetSymbolAddress((void**)&px, g_x);
    cudaGetSymbolAddress((void**)&pm, g_m);
    cudaGetSymbolAddress((void**)&pns, g_ns);
    cudaGetSymbolAddress((void**)&pnd, g_nd);
    cudaGetSymbolAddress((void**)&psum, g_sum);
    cudaGetSymbolAddress((void**)&psumsq, g_sumsq);

    const int nd4 = (Nn * DDIM) / 4;                 // x/m buffer in float4s
    const int elems = Nn * DDIM;

    // --- degree norms ---
    zero_kernel<<<(Nn / 4 + 255) / 256, 256>>>(pns, Nn / 4);
    zero_kernel<<<(Nn / 4 + 255) / 256, 256>>>(pnd, Nn / 4);
    degree_kernel<<<(E + 255) / 256, 256>>>(src, dst, pns, pnd, E);
    norm_fin_kernel<<<(Nn + 255) / 256, 256>>>(pns, pnd, Nn);

    // --- x = feat @ W_fc + b_fc ---
    gemm_kernel<false><<<gemm_grid(Nn, DDIM), 256>>>(feat, nullptr, W_fc, b_fc, px, Nn, DDIM, F);

    // --- layer 1: gconv + bn_elu ---
    zero_kernel<<<(nd4 + 255) / 256, 256>>>(pm, nd4);
    scatter_kernel<<<(E * 32 + 255) / 256, 256>>>(px, pns, src, dst, pm, E);
    gemm_kernel<true><<<gemm_grid(Nn, DDIM), 256>>>(pm, pnd, W1, b1, px, Nn, DDIM, DDIM);
    zero_kernel<<<1, 128>>>(psum, DDIM / 4);
    zero_kernel<<<1, 128>>>(psumsq, DDIM / 4);
    bn_stats_kernel<<<512, DDIM>>>(px, psum, psumsq, Nn);
    bn_elu_kernel<<<(elems + 255) / 256, 256>>>(px, psum, psumsq, gamma, beta, Nn);

    // --- layer 2: gconv + bn_elu ---
    zero_kernel<<<(nd4 + 255) / 256, 256>>>(pm, nd4);
    scatter_kernel<<<(E * 32 + 255) / 256, 256>>>(px, pns, src, dst, pm, E);
    gemm_kernel<true><<<gemm_grid(Nn, DDIM), 256>>>(pm, pnd, W2, b2, px, Nn, DDIM, DDIM);
    zero_kernel<<<1, 128>>>(psum, DDIM / 4);
    zero_kernel<<<1, 128>>>(psumsq, DDIM / 4);
    bn_stats_kernel<<<512, DDIM>>>(px, psum, psumsq, Nn);
    bn_elu_kernel<<<(elems + 255) / 256, 256>>>(px, psum, psumsq, gamma, beta, Nn);

    // --- layer 3: gconv (output -> d_out x region) ---
    zero_kernel<<<(nd4 + 255) / 256, 256>>>(pm, nd4);
    scatter_kernel<<<(E * 32 + 255) / 256, 256>>>(px, pns, src, dst, pm, E);
    gemm_kernel<true><<<gemm_grid(Nn, DDIM), 256>>>(pm, pnd, W3, b3, out_x, Nn, DDIM, DDIM);

    // --- logits = x @ W_lin + b_lin ---
    gemm_kernel<false><<<gemm_grid(Nn, C), 256>>>(out_x, nullptr, W_lin, b_lin, out_logits, Nn, C, DDIM);
}

// round 10
// speedup vs baseline: 1.3716x; 1.3716x over previous
#include <cuda_runtime.h>
#include <cuda_bf16.h>
#include <math.h>
#include <stdint.h>

#define NMAX 50000
#define DDIM 256
#define FDIM 1024

// ---------------- scratch (no allocations allowed) ----------------
__device__ float g_x[NMAX * DDIM];
__device__ float g_m[NMAX * DDIM];
__device__ float g_ns[NMAX];
__device__ float g_nd[NMAX];
__device__ float g_sum[DDIM];
__device__ float g_sumsq[DDIM];
__device__ __nv_bfloat16 g_ahi[(size_t)NMAX * FDIM];
__device__ __nv_bfloat16 g_alo[(size_t)NMAX * FDIM];
__device__ __nv_bfloat16 g_bthi[DDIM * FDIM];   // W^T hi  [N=256][K]
__device__ __nv_bfloat16 g_btlo[DDIM * FDIM];   // W^T lo

// ---------------- helpers ----------------
__device__ __forceinline__ uint32_t smem_u32(const void* p) {
    uint32_t a;
    asm("{ .reg .u64 t; cvta.to.shared.u64 t, %1; cvt.u32.u64 %0, t; }" : "=r"(a) : "l"(p));
    return a;
}
__device__ __forceinline__ void cp16(uint32_t saddr, const void* g) {
    asm volatile("cp.async.cg.shared.global [%0], [%1], 16;" :: "r"(saddr), "l"(g) : "memory");
}
__device__ __forceinline__ void ldsm_x4(uint32_t* r, uint32_t addr) {
    asm volatile("ldmatrix.sync.aligned.m8n8.x4.shared.b16 {%0,%1,%2,%3}, [%4];"
                 : "=r"(r[0]), "=r"(r[1]), "=r"(r[2]), "=r"(r[3]) : "r"(addr));
}
__device__ __forceinline__ void mma16816(float* c, const uint32_t* a, uint32_t b0, uint32_t b1) {
    asm volatile(
        "mma.sync.aligned.m16n8k16.row.col.f32.bf16.bf16.f32 "
        "{%0,%1,%2,%3}, {%4,%5,%6,%7}, {%8,%9}, {%0,%1,%2,%3};"
        : "+f"(c[0]), "+f"(c[1]), "+f"(c[2]), "+f"(c[3])
        : "r"(a[0]), "r"(a[1]), "r"(a[2]), "r"(a[3]), "r"(b0), "r"(b1));
}

// ---------------- bf16 split-precision MMA GEMM ----------------
// C[M,256] = A[M,K] @ W[K,256] + bias, A/W given as bf16 hi/lo splits (W transposed [256][K]).
// CTA tile 128x128, BK=32, 8 warps (warp tile 64x32), cp.async double buffer.
#define PITCH 80                      // bytes per 32-bf16 smem row (bank-conflict-free ldmatrix)
#define TILE_BYTES (128 * PITCH)      // 10240
#define STAGE_BYTES (4 * TILE_BYTES)  // Ah, Al, Bh, Bl
#define MMA_SMEM (2 * STAGE_BYTES)    // 81920

__global__ __launch_bounds__(256, 1)
void gemm_mma_kernel(const __nv_bfloat16* __restrict__ Ahi, const __nv_bfloat16* __restrict__ Alo,
                     const __nv_bfloat16* __restrict__ Bthi, const __nv_bfloat16* __restrict__ Btlo,
                     const float* __restrict__ bias, float* __restrict__ C, int M, int K) {
    extern __shared__ char smem[];
    uint32_t sbase = smem_u32(smem);
    int tid = threadIdx.x, wid = tid >> 5, lane = tid & 31;
    int warp_m = wid & 1, warp_n = wid >> 1;
    int row0 = blockIdx.y * 128, col0 = blockIdx.x * 128;

    float acc[4][4][4];
#pragma unroll
    for (int i = 0; i < 4; i++)
#pragma unroll
        for (int j = 0; j < 4; j++)
#pragma unroll
            for (int q = 0; q < 4; q++) acc[i][j][q] = 0.f;

    const int NC = K >> 5;

    // ldmatrix per-lane offsets (within a 16x16 bf16 block)
    int lr = lane & 7, g = lane >> 3;
    uint32_t a_off = (uint32_t)((((g & 1) << 3) + lr) * PITCH + (((g >> 1) << 3) << 1));
    uint32_t b_off = (uint32_t)((((g >> 1) << 3) + lr) * PITCH + (((g & 1) << 3) << 1));

    // stage loader: 2 x 16B per thread per tile
    auto load_stage = [&](int buf, int k0) {
#pragma unroll
        for (int i = 0; i < 2; i++) {
            int u = tid + i * 256;
            int r = u >> 2, ch = u & 3;
            uint32_t soff = (uint32_t)(buf * STAGE_BYTES + r * PITCH + ch * 16);
            int ra = row0 + r; if (ra > M - 1) ra = M - 1;     // clamp tail rows
            size_t ga = (size_t)ra * K + k0 + ch * 8;
            cp16(sbase + soff, Ahi + ga);
            cp16(sbase + TILE_BYTES + soff, Alo + ga);
            size_t gb = (size_t)(col0 + r) * K + k0 + ch * 8;
            cp16(sbase + 2 * TILE_BYTES + soff, Bthi + gb);
            cp16(sbase + 3 * TILE_BYTES + soff, Btlo + gb);
        }
        asm volatile("cp.async.commit_group;" ::: "memory");
    };

    load_stage(0, 0);

    for (int c = 0; c < NC; c++) {
        if (c + 1 < NC) {
            load_stage((c + 1) & 1, (c + 1) * 32);
            asm volatile("cp.async.wait_group 1;" ::: "memory");
        } else {
            asm volatile("cp.async.wait_group 0;" ::: "memory");
        }
        __syncthreads();

        uint32_t sb = sbase + (uint32_t)((c & 1) * STAGE_BYTES);
#pragma unroll
        for (int kk = 0; kk < 2; kk++) {
            uint32_t kb = (uint32_t)(kk * 32);  // 16 bf16 = 32B
            uint32_t ah[4][4], al[4][4], bh[2][4], bl[2][4];
#pragma unroll
            for (int mt = 0; mt < 4; mt++) {
                uint32_t aaddr = sb + (uint32_t)((warp_m * 64 + mt * 16) * PITCH) + kb + a_off;
                ldsm_x4(ah[mt], aaddr);
                ldsm_x4(al[mt], aaddr + TILE_BYTES);
            }
#pragma unroll
            for (int bt = 0; bt < 2; bt++) {
                uint32_t baddr = sb + 2 * TILE_BYTES +
                                 (uint32_t)((warp_n * 32 + bt * 16) * PITCH) + kb + b_off;
                ldsm_x4(bh[bt], baddr);
                ldsm_x4(bl[bt], baddr + TILE_BYTES);
            }
#pragma unroll
            for (int mt = 0; mt < 4; mt++)
#pragma unroll
                for (int nj = 0; nj < 4; nj++) {
                    int bt = nj >> 1, h = (nj & 1) * 2;
                    mma16816(acc[mt][nj], ah[mt], bh[bt][h], bh[bt][h + 1]);
                    mma16816(acc[mt][nj], ah[mt], bl[bt][h], bl[bt][h + 1]);
                    mma16816(acc[mt][nj], al[mt], bh[bt][h], bh[bt][h + 1]);
                }
        }
        __syncthreads();
    }

    // epilogue
    int g2 = lane >> 2, tig = lane & 3;
#pragma unroll
    for (int mt = 0; mt < 4; mt++) {
#pragma unroll
        for (int nj = 0; nj < 4; nj++) {
            int r = row0 + warp_m * 64 + mt * 16 + g2;
            int cg = col0 + warp_n * 32 + nj * 8 + tig * 2;
            float2 bv = *reinterpret_cast<const float2*>(bias + cg);
            if (r < M) {
                float2 o = make_float2(acc[mt][nj][0] + bv.x, acc[mt][nj][1] + bv.y);
                *reinterpret_cast<float2*>(C + (size_t)r * 256 + cg) = o;
            }
            if (r + 8 < M) {
                float2 o = make_float2(acc[mt][nj][2] + bv.x, acc[mt][nj][3] + bv.y);
                *reinterpret_cast<float2*>(C + (size_t)(r + 8) * 256 + cg) = o;
            }
        }
    }
}

// ---------------- fp32 -> bf16 hi/lo split kernels ----------------
__global__ void split_a_kernel(const float* __restrict__ A, const float* __restrict__ rs,
                               __nv_bfloat16* __restrict__ hi, __nv_bfloat16* __restrict__ lo,
                               int total, int kshift) {
    int i = blockIdx.x * blockDim.x + threadIdx.x;
    if (i >= total) return;
    float a = A[i];
    if (rs) a *= rs[i >> kshift];
    __nv_bfloat16 h = __float2bfloat16(a);
    hi[i] = h;
    lo[i] = __float2bfloat16(a - __bfloat162float(h));
}

__global__ void split_w_kernel(const float* __restrict__ W, __nv_bfloat16* __restrict__ thi,
                               __nv_bfloat16* __restrict__ tlo, int K, int N, int kshift) {
    int i = blockIdx.x * blockDim.x + threadIdx.x;
    if (i >= N * K) return;
    int n = i >> kshift;
    int k = i & (K - 1);
    float w = W[(size_t)k * N + n];
    __nv_bfloat16 h = __float2bfloat16(w);
    thi[i] = h;
    tlo[i] = __float2bfloat16(w - __bfloat162float(h));
}

// ---------------- graph/BN kernels (unchanged) ----------------
__global__ void zero_kernel(float* __restrict__ p, int n4) {
    int i = blockIdx.x * blockDim.x + threadIdx.x;
    if (i < n4) reinterpret_cast<float4*>(p)[i] = make_float4(0.f, 0.f, 0.f, 0.f);
}

__global__ void degree_kernel(const int* __restrict__ src, const int* __restrict__ dst,
                              float* __restrict__ ns, float* __restrict__ nd, int E) {
    int e = blockIdx.x * blockDim.x + threadIdx.x;
    if (e < E) {
        atomicAdd(&ns[src[e]], 1.f);
        atomicAdd(&nd[dst[e]], 1.f);
    }
}

__global__ void norm_fin_kernel(float* __restrict__ ns, float* __restrict__ nd, int n) {
    int i = blockIdx.x * blockDim.x + threadIdx.x;
    if (i < n) {
        ns[i] = rsqrtf(fmaxf(ns[i], 1.f));
        nd[i] = rsqrtf(fmaxf(nd[i], 1.f));
    }
}

__global__ void scatter_kernel(const float* __restrict__ x, const float* __restrict__ ns,
                               const int* __restrict__ src, const int* __restrict__ dst,
                               float* __restrict__ m, int E) {
    int gw = (blockIdx.x * blockDim.x + threadIdx.x) >> 5;
    int lane = threadIdx.x & 31;
    if (gw >= E) return;
    int s = src[gw];
    int d = dst[gw];
    float sc = ns[s];
    const float* xs = x + (size_t)s * DDIM;
    float* md = m + (size_t)d * DDIM;
    float v[DDIM / 32];
#pragma unroll
    for (int j = 0; j < DDIM / 32; j++) v[j] = xs[lane + j * 32];
#pragma unroll
    for (int j = 0; j < DDIM / 32; j++) atomicAdd(md + lane + j * 32, v[j] * sc);
}

__global__ void bn_stats_kernel(const float* __restrict__ x, float* __restrict__ sum,
                                float* __restrict__ sumsq, int rows) {
    int col = threadIdx.x;
    float s = 0.f, s2 = 0.f;
    for (int r = blockIdx.x; r < rows; r += gridDim.x) {
        float v = x[(size_t)r * DDIM + col];
        s += v;
        s2 += v * v;
    }
    atomicAdd(&sum[col], s);
    atomicAdd(&sumsq[col], s2);
}

__global__ void bn_elu_kernel(float* __restrict__ x, const float* __restrict__ sum,
                              const float* __restrict__ sumsq, const float* __restrict__ gamma,
                              const float* __restrict__ beta, int rows) {
    int idx = blockIdx.x * blockDim.x + threadIdx.x;
    int total = rows * DDIM;
    if (idx >= total) return;
    int col = idx & (DDIM - 1);
    float inv_n = 1.f / (float)rows;
    float mu = sum[col] * inv_n;
    float var = sumsq[col] * inv_n - mu * mu;
    float y = gamma[col] * (x[idx] - mu) * rsqrtf(var + 1e-5f) + beta[col];
    x[idx] = (y > 0.f) ? y : expm1f(y);
}

// ---------------- fp32 tiled GEMM (logits, N=40) ----------------
__global__ __launch_bounds__(256) void gemm_simt_kernel(
    const float* __restrict__ A, const float* __restrict__ B, const float* __restrict__ bias,
    float* __restrict__ C, int M, int N, int K) {
    __shared__ float As[16][68];
    __shared__ float Bs[16][64];
    int tid = threadIdx.x;
    int tx = tid & 15, ty = tid >> 4;
    int row0 = blockIdx.y * 64, col0 = blockIdx.x * 64;
    int arow = tid >> 2, ak4 = (tid & 3) * 4;
    int brow = tid >> 4, bc4 = (tid & 15) * 4;

    float acc[4][4];
#pragma unroll
    for (int i = 0; i < 4; i++)
#pragma unroll
        for (int j = 0; j < 4; j++) acc[i][j] = 0.f;

    for (int k0 = 0; k0 < K; k0 += 16) {
        float4 a = make_float4(0.f, 0.f, 0.f, 0.f);
        if (row0 + arow < M)
            a = *reinterpret_cast<const float4*>(A + (size_t)(row0 + arow) * K + k0 + ak4);
        As[ak4 + 0][arow] = a.x; As[ak4 + 1][arow] = a.y;
        As[ak4 + 2][arow] = a.z; As[ak4 + 3][arow] = a.w;
        float4 b = make_float4(0.f, 0.f, 0.f, 0.f);
        if (col0 + bc4 < N)
            b = *reinterpret_cast<const float4*>(B + (size_t)(k0 + brow) * N + col0 + bc4);
        *reinterpret_cast<float4*>(&Bs[brow][bc4]) = b;
        __syncthreads();
#pragma unroll
        for (int kk = 0; kk < 16; kk++) {
            float4 ra = *reinterpret_cast<const float4*>(&As[kk][ty * 4]);
            float4 rb = *reinterpret_cast<const float4*>(&Bs[kk][tx * 4]);
            float av[4] = {ra.x, ra.y, ra.z, ra.w};
            float bv[4] = {rb.x, rb.y, rb.z, rb.w};
#pragma unroll
            for (int i = 0; i < 4; i++)
#pragma unroll
                for (int j = 0; j < 4; j++) acc[i][j] += av[i] * bv[j];
        }
        __syncthreads();
    }
    int c0 = col0 + tx * 4;
    if (c0 < N) {
        float4 bv = *reinterpret_cast<const float4*>(bias + c0);
#pragma unroll
        for (int i = 0; i < 4; i++) {
            int r = row0 + ty * 4 + i;
            if (r < M) {
                float4 o;
                o.x = acc[i][0] + bv.x; o.y = acc[i][1] + bv.y;
                o.z = acc[i][2] + bv.z; o.w = acc[i][3] + bv.w;
                *reinterpret_cast<float4*>(C + (size_t)r * N + c0) = o;
            }
        }
    }
}

// ---------------- host orchestration ----------------
extern "C" void kernel_launch(void* const* d_in, const int* in_sizes, int n_in,
                              void* d_out, int out_size) {
    const float* feat  = (const float*)d_in[0];
    const int*   src   = (const int*)d_in[1];
    const int*   dst   = (const int*)d_in[2];
    const float* W_fc  = (const float*)d_in[3];
    const float* b_fc  = (const float*)d_in[4];
    const float* W1    = (const float*)d_in[5];
    const float* b1    = (const float*)d_in[6];
    const float* W2    = (const float*)d_in[7];
    const float* b2    = (const float*)d_in[8];
    const float* W3    = (const float*)d_in[9];
    const float* b3    = (const float*)d_in[10];
    const float* gamma = (const float*)d_in[11];
    const float* beta  = (const float*)d_in[12];
    const float* W_lin = (const float*)d_in[13];
    const float* b_lin = (const float*)d_in[14];

    const int Nn = in_sizes[0] / FDIM;      // 50000
    const int E = in_sizes[1];              // 300000
    const int C = in_sizes[13] / DDIM;      // 40

    float* out_x = (float*)d_out;
    float* out_logits = out_x + (size_t)Nn * DDIM;

    float *px, *pm, *pns, *pnd, *psum, *psumsq;
    __nv_bfloat16 *pahi, *palo, *pbthi, *pbtlo;
    cudaGetSymbolAddress((void**)&px, g_x);
    cudaGetSymbolAddress((void**)&pm, g_m);
    cudaGetSymbolAddress((void**)&pns, g_ns);
    cudaGetSymbolAddress((void**)&pnd, g_nd);
    cudaGetSymbolAddress((void**)&psum, g_sum);
    cudaGetSymbolAddress((void**)&psumsq, g_sumsq);
    cudaGetSymbolAddress((void**)&pahi, g_ahi);
    cudaGetSymbolAddress((void**)&palo, g_alo);
    cudaGetSymbolAddress((void**)&pbthi, g_bthi);
    cudaGetSymbolAddress((void**)&pbtlo, g_btlo);

    cudaFuncSetAttribute(gemm_mma_kernel, cudaFuncAttributeMaxDynamicSharedMemorySize, MMA_SMEM);

    const int nd4 = (Nn * DDIM) / 4;
    const int elems = Nn * DDIM;
    dim3 ggrid(2, (Nn + 127) / 128);        // 2 col-blocks x 391 row-blocks

    // --- degree norms ---
    zero_kernel<<<(Nn / 4 + 255) / 256, 256>>>(pns, Nn / 4);
    zero_kernel<<<(Nn / 4 + 255) / 256, 256>>>(pnd, Nn / 4);
    degree_kernel<<<(E + 255) / 256, 256>>>(src, dst, pns, pnd, E);
    norm_fin_kernel<<<(Nn + 255) / 256, 256>>>(pns, pnd, Nn);

    // --- x = feat @ W_fc + b_fc (bf16 split MMA, K=1024) ---
    split_w_kernel<<<(DDIM * FDIM + 255) / 256, 256>>>(W_fc, pbthi, pbtlo, FDIM, DDIM, 10);
    split_a_kernel<<<(Nn * FDIM + 255) / 256, 256>>>(feat, nullptr, pahi, palo, Nn * FDIM, 10);
    gemm_mma_kernel<<<ggrid, 256, MMA_SMEM>>>(pahi, palo, pbthi, pbtlo, b_fc, px, Nn, FDIM);

    // --- layer 1 ---
    zero_kernel<<<(nd4 + 255) / 256, 256>>>(pm, nd4);
    scatter_kernel<<<(E * 32 + 255) / 256, 256>>>(px, pns, src, dst, pm, E);
    split_w_kernel<<<(DDIM * DDIM + 255) / 256, 256>>>(W1, pbthi, pbtlo, DDIM, DDIM, 8);
    split_a_kernel<<<(elems + 255) / 256, 256>>>(pm, pnd, pahi, palo, elems, 8);
    gemm_mma_kernel<<<ggrid, 256, MMA_SMEM>>>(pahi, palo, pbthi, pbtlo, b1, px, Nn, DDIM);
    zero_kernel<<<1, 128>>>(psum, DDIM / 4);
    zero_kernel<<<1, 128>>>(psumsq, DDIM / 4);
    bn_stats_kernel<<<512, DDIM>>>(px, psum, psumsq, Nn);
    bn_elu_kernel<<<(elems + 255) / 256, 256>>>(px, psum, psumsq, gamma, beta, Nn);

    // --- layer 2 ---
    zero_kernel<<<(nd4 + 255) / 256, 256>>>(pm, nd4);
    scatter_kernel<<<(E * 32 + 255) / 256, 256>>>(px, pns, src, dst, pm, E);
    split_w_kernel<<<(DDIM * DDIM + 255) / 256, 256>>>(W2, pbthi, pbtlo, DDIM, DDIM, 8);
    split_a_kernel<<<(elems + 255) / 256, 256>>>(pm, pnd, pahi, palo, elems, 8);
    gemm_mma_kernel<<<ggrid, 256, MMA_SMEM>>>(pahi, palo, pbthi, pbtlo, b2, px, Nn, DDIM);
    zero_kernel<<<1, 128>>>(psum, DDIM / 4);
    zero_kernel<<<1, 128>>>(psumsq, DDIM / 4);
    bn_stats_kernel<<<512, DDIM>>>(px, psum, psumsq, Nn);
    bn_elu_kernel<<<(elems + 255) / 256, 256>>>(px, psum, psumsq, gamma, beta, Nn);

    // --- layer 3 (output x -> d_out) ---
    zero_kernel<<<(nd4 + 255) / 256, 256>>>(pm, nd4);
    scatter_kernel<<<(E * 32 + 255) / 256, 256>>>(px, pns, src, dst, pm, E);
    split_w_kernel<<<(DDIM * DDIM + 255) / 256, 256>>>(W3, pbthi, pbtlo, DDIM, DDIM, 8);
    split_a_kernel<<<(elems + 255) / 256, 256>>>(pm, pnd, pahi, palo, elems, 8);
    gemm_mma_kernel<<<ggrid, 256, MMA_SMEM>>>(pahi, palo, pbthi, pbtlo, b3, out_x, Nn, DDIM);

    // --- logits = x @ W_lin + b_lin (SIMT, N=40) ---
    gemm_simt_kernel<<<dim3((C + 63) / 64, (Nn + 63) / 64), 256>>>(out_x, W_lin, b_lin,
                                                                   out_logits, Nn, C, DDIM);
}

// round 13
// speedup vs baseline: 1.4173x; 1.0333x over previous
#include <cuda_runtime.h>
#include <cuda_bf16.h>
#include <math.h>
#include <stdint.h>

#define NMAX 50000
#define DDIM 256
#define FDIM 1024

// ---------------- scratch (no allocations allowed) ----------------
__device__ float g_x[NMAX * DDIM];
__device__ float g_m[NMAX * DDIM];
__device__ float g_ns[NMAX];
__device__ float g_nd[NMAX];
__device__ float g_sum[DDIM];
__device__ float g_sumsq[DDIM];
__device__ __nv_bfloat16 g_bthi[DDIM * FDIM];   // W^T hi  [N=256][K]
__device__ __nv_bfloat16 g_btlo[DDIM * FDIM];   // W^T lo

// ---------------- helpers ----------------
__device__ __forceinline__ uint32_t smem_u32(const void* p) {
    uint32_t a;
    asm("{ .reg .u64 t; cvta.to.shared.u64 t, %1; cvt.u32.u64 %0, t; }" : "=r"(a) : "l"(p));
    return a;
}
__device__ __forceinline__ void cp16(uint32_t saddr, const void* g) {
    asm volatile("cp.async.cg.shared.global [%0], [%1], 16;" :: "r"(saddr), "l"(g) : "memory");
}
__device__ __forceinline__ void ldsm_x4(uint32_t* r, uint32_t addr) {
    asm volatile("ldmatrix.sync.aligned.m8n8.x4.shared.b16 {%0,%1,%2,%3}, [%4];"
                 : "=r"(r[0]), "=r"(r[1]), "=r"(r[2]), "=r"(r[3]) : "r"(addr));
}
__device__ __forceinline__ void mma16816(float* c, const uint32_t* a, uint32_t b0, uint32_t b1) {
    asm volatile(
        "mma.sync.aligned.m16n8k16.row.col.f32.bf16.bf16.f32 "
        "{%0,%1,%2,%3}, {%4,%5,%6,%7}, {%8,%9}, {%0,%1,%2,%3};"
        : "+f"(c[0]), "+f"(c[1]), "+f"(c[2]), "+f"(c[3])
        : "r"(a[0]), "r"(a[1]), "r"(a[2]), "r"(a[3]), "r"(b0), "r"(b1));
}
__device__ __forceinline__ uint32_t pack_bf2(float a, float b) {
    return ((uint32_t)__bfloat16_as_ushort(__float2bfloat16(b)) << 16) |
           (uint32_t)__bfloat16_as_ushort(__float2bfloat16(a));
}

// ---------------- bf16 split-precision MMA GEMM (fused fp32->hi/lo A conversion) -------------
// C[M,256] = (A[M,K] * rowscale) @ W[K,256] + bias.
// A is fp32 in global; converted to bf16 hi/lo in the loader (same HBM bytes as pre-split).
// W given as transposed bf16 hi/lo splits [256][K] (tiny, pre-split once).
// CTA tile 128x128, BK=32, 8 warps (warp tile 64x32), double buffer; B via cp.async,
// A LDGs issued before the MMA section and converted/stored after it (latency hidden).
#define PITCH 80                      // bytes per 32-bf16 smem row (bank-conflict-free ldmatrix)
#define TILE_BYTES (128 * PITCH)      // 10240
#define STAGE_BYTES (4 * TILE_BYTES)  // Ah, Al, Bh, Bl
#define MMA_SMEM (2 * STAGE_BYTES)    // 81920

__global__ __launch_bounds__(256, 1)
void gemm_mma_kernel(const float* __restrict__ A, const float* __restrict__ rowscale,
                     const __nv_bfloat16* __restrict__ Bthi, const __nv_bfloat16* __restrict__ Btlo,
                     const float* __restrict__ bias, float* __restrict__ C, int M, int K) {
    extern __shared__ char smem[];
    uint32_t sbase = smem_u32(smem);
    int tid = threadIdx.x, wid = tid >> 5, lane = tid & 31;
    int warp_m = wid & 1, warp_n = wid >> 1;
    int row0 = blockIdx.y * 128, col0 = blockIdx.x * 128;

    float acc[4][4][4];
#pragma unroll
    for (int i = 0; i < 4; i++)
#pragma unroll
        for (int j = 0; j < 4; j++)
#pragma unroll
            for (int q = 0; q < 4; q++) acc[i][j][q] = 0.f;

    const int NC = K >> 5;

    // ldmatrix per-lane offsets (within a 16x16 bf16 block)
    int lr = lane & 7, g = lane >> 3;
    uint32_t a_off = (uint32_t)((((g & 1) << 3) + lr) * PITCH + (((g >> 1) << 3) << 1));
    uint32_t b_off = (uint32_t)((((g >> 1) << 3) + lr) * PITCH + (((g & 1) << 3) << 1));

    // A loader mapping: thread -> (row = tid>>1, 16 consecutive k at hf = (tid&1)*16)
    int arow = tid >> 1, ahf = (tid & 1) * 16;
    int ra = row0 + arow; if (ra > M - 1) ra = M - 1;   // clamp tail (stores guarded)
    float ascale = rowscale ? rowscale[ra] : 1.f;
    const float* aptr = A + (size_t)ra * K + ahf;

    // B loader: 4 cp.async x 16B per thread per stage (hi+lo)
    auto load_B = [&](int buf, int k0) {
#pragma unroll
        for (int i = 0; i < 2; i++) {
            int u = tid + i * 256;
            int r = u >> 2, ch = u & 3;
            uint32_t soff = (uint32_t)(buf * STAGE_BYTES + r * PITCH + ch * 16);
            size_t gb = (size_t)(col0 + r) * K + k0 + ch * 8;
            cp16(sbase + 2 * TILE_BYTES + soff, Bthi + gb);
            cp16(sbase + 3 * TILE_BYTES + soff, Btlo + gb);
        }
        asm volatile("cp.async.commit_group;" ::: "memory");
    };
    // A: issue LDGs (held in regs)
    auto load_A = [&](int k0, float4* v) {
        const float4* ap = reinterpret_cast<const float4*>(aptr + k0);
#pragma unroll
        for (int q = 0; q < 4; q++) {
            float4 t = ap[q];
            t.x *= ascale; t.y *= ascale; t.z *= ascale; t.w *= ascale;
            v[q] = t;
        }
    };
    // A: convert to hi/lo and store to smem
    auto store_A = [&](int buf, const float4* v) {
        char* hp = smem + buf * STAGE_BYTES + arow * PITCH + ahf * 2;
#pragma unroll
        for (int q = 0; q < 4; q++) {
            float4 t = v[q];
            float hx = __bfloat162float(__float2bfloat16(t.x));
            float hy = __bfloat162float(__float2bfloat16(t.y));
            float hz = __bfloat162float(__float2bfloat16(t.z));
            float hw = __bfloat162float(__float2bfloat16(t.w));
            uint2 h = make_uint2(pack_bf2(t.x, t.y), pack_bf2(t.z, t.w));
            uint2 l = make_uint2(pack_bf2(t.x - hx, t.y - hy), pack_bf2(t.z - hz, t.w - hw));
            *reinterpret_cast<uint2*>(hp + q * 8) = h;
            *reinterpret_cast<uint2*>(hp + TILE_BYTES + q * 8) = l;
        }
    };

    // prologue: stage 0 fully populated
    float4 va[4];
    load_B(0, 0);
    load_A(0, va);
    store_A(0, va);

    for (int c = 0; c < NC; c++) {
        bool pre = (c + 1 < NC);
        if (pre) {
            load_B((c + 1) & 1, (c + 1) * 32);
            load_A((c + 1) * 32, va);            // LDGs in flight during MMA below
            asm volatile("cp.async.wait_group 1;" ::: "memory");
        } else {
            asm volatile("cp.async.wait_group 0;" ::: "memory");
        }
        __syncthreads();

        uint32_t sb = sbase + (uint32_t)((c & 1) * STAGE_BYTES);
#pragma unroll
        for (int kk = 0; kk < 2; kk++) {
            uint32_t kb = (uint32_t)(kk * 32);  // 16 bf16 = 32B
            uint32_t ah[4][4], al[4][4], bh[2][4], bl[2][4];
#pragma unroll
            for (int mt = 0; mt < 4; mt++) {
                uint32_t aaddr = sb + (uint32_t)((warp_m * 64 + mt * 16) * PITCH) + kb + a_off;
                ldsm_x4(ah[mt], aaddr);
                ldsm_x4(al[mt], aaddr + TILE_BYTES);
            }
#pragma unroll
            for (int bt = 0; bt < 2; bt++) {
                uint32_t baddr = sb + 2 * TILE_BYTES +
                                 (uint32_t)((warp_n * 32 + bt * 16) * PITCH) + kb + b_off;
                ldsm_x4(bh[bt], baddr);
                ldsm_x4(bl[bt], baddr + TILE_BYTES);
            }
#pragma unroll
            for (int mt = 0; mt < 4; mt++)
#pragma unroll
                for (int nj = 0; nj < 4; nj++) {
                    int bt = nj >> 1, h = (nj & 1) * 2;
                    mma16816(acc[mt][nj], ah[mt], bh[bt][h], bh[bt][h + 1]);
                    mma16816(acc[mt][nj], ah[mt], bl[bt][h], bl[bt][h + 1]);
                    mma16816(acc[mt][nj], al[mt], bh[bt][h], bh[bt][h + 1]);
                }
        }
        if (pre) store_A((c + 1) & 1, va);      // convert after MMAs: LDG latency hidden
        __syncthreads();
    }

    // epilogue
    int g2 = lane >> 2, tig = lane & 3;
#pragma unroll
    for (int mt = 0; mt < 4; mt++) {
#pragma unroll
        for (int nj = 0; nj < 4; nj++) {
            int r = row0 + warp_m * 64 + mt * 16 + g2;
            int cg = col0 + warp_n * 32 + nj * 8 + tig * 2;
            float2 bv = *reinterpret_cast<const float2*>(bias + cg);
            if (r < M) {
                float2 o = make_float2(acc[mt][nj][0] + bv.x, acc[mt][nj][1] + bv.y);
                *reinterpret_cast<float2*>(C + (size_t)r * 256 + cg) = o;
            }
            if (r + 8 < M) {
                float2 o = make_float2(acc[mt][nj][2] + bv.x, acc[mt][nj][3] + bv.y);
                *reinterpret_cast<float2*>(C + (size_t)(r + 8) * 256 + cg) = o;
            }
        }
    }
}

// ---------------- W[K,N] -> W^T bf16 hi/lo splits [N,K] ----------------
__global__ void split_w_kernel(const float* __restrict__ W, __nv_bfloat16* __restrict__ thi,
                               __nv_bfloat16* __restrict__ tlo, int K, int N, int kshift) {
    int i = blockIdx.x * blockDim.x + threadIdx.x;
    if (i >= N * K) return;
    int n = i >> kshift;
    int k = i & (K - 1);
    float w = W[(size_t)k * N + n];
    __nv_bfloat16 h = __float2bfloat16(w);
    thi[i] = h;
    tlo[i] = __float2bfloat16(w - __bfloat162float(h));
}

// ---------------- graph/BN kernels (unchanged) ----------------
__global__ void zero_kernel(float* __restrict__ p, int n4) {
    int i = blockIdx.x * blockDim.x + threadIdx.x;
    if (i < n4) reinterpret_cast<float4*>(p)[i] = make_float4(0.f, 0.f, 0.f, 0.f);
}

__global__ void degree_kernel(const int* __restrict__ src, const int* __restrict__ dst,
                              float* __restrict__ ns, float* __restrict__ nd, int E) {
    int e = blockIdx.x * blockDim.x + threadIdx.x;
    if (e < E) {
        atomicAdd(&ns[src[e]], 1.f);
        atomicAdd(&nd[dst[e]], 1.f);
    }
}

__global__ void norm_fin_kernel(float* __restrict__ ns, float* __restrict__ nd, int n) {
    int i = blockIdx.x * blockDim.x + threadIdx.x;
    if (i < n) {
        ns[i] = rsqrtf(fmaxf(ns[i], 1.f));
        nd[i] = rsqrtf(fmaxf(nd[i], 1.f));
    }
}

__global__ void scatter_kernel(const float* __restrict__ x, const float* __restrict__ ns,
                               const int* __restrict__ src, const int* __restrict__ dst,
                               float* __restrict__ m, int E) {
    int gw = (blockIdx.x * blockDim.x + threadIdx.x) >> 5;
    int lane = threadIdx.x & 31;
    if (gw >= E) return;
    int s = src[gw];
    int d = dst[gw];
    float sc = ns[s];
    const float* xs = x + (size_t)s * DDIM;
    float* md = m + (size_t)d * DDIM;
    float v[DDIM / 32];
#pragma unroll
    for (int j = 0; j < DDIM / 32; j++) v[j] = xs[lane + j * 32];
#pragma unroll
    for (int j = 0; j < DDIM / 32; j++) atomicAdd(md + lane + j * 32, v[j] * sc);
}

__global__ void bn_stats_kernel(const float* __restrict__ x, float* __restrict__ sum,
                                float* __restrict__ sumsq, int rows) {
    int col = threadIdx.x;
    float s = 0.f, s2 = 0.f;
    for (int r = blockIdx.x; r < rows; r += gridDim.x) {
        float v = x[(size_t)r * DDIM + col];
        s += v;
        s2 += v * v;
    }
    atomicAdd(&sum[col], s);
    atomicAdd(&sumsq[col], s2);
}

__global__ void bn_elu_kernel(float* __restrict__ x, const float* __restrict__ sum,
                              const float* __restrict__ sumsq, const float* __restrict__ gamma,
                              const float* __restrict__ beta, int rows) {
    int idx = blockIdx.x * blockDim.x + threadIdx.x;
    int total = rows * DDIM;
    if (idx >= total) return;
    int col = idx & (DDIM - 1);
    float inv_n = 1.f / (float)rows;
    float mu = sum[col] * inv_n;
    float var = sumsq[col] * inv_n - mu * mu;
    float y = gamma[col] * (x[idx] - mu) * rsqrtf(var + 1e-5f) + beta[col];
    x[idx] = (y > 0.f) ? y : expm1f(y);
}

// ---------------- fp32 tiled GEMM (logits, N=40) ----------------
__global__ __launch_bounds__(256) void gemm_simt_kernel(
    const float* __restrict__ A, const float* __restrict__ B, const float* __restrict__ bias,
    float* __restrict__ C, int M, int N, int K) {
    __shared__ float As[16][68];
    __shared__ float Bs[16][64];
    int tid = threadIdx.x;
    int tx = tid & 15, ty = tid >> 4;
    int row0 = blockIdx.y * 64, col0 = blockIdx.x * 64;
    int arow = tid >> 2, ak4 = (tid & 3) * 4;
    int brow = tid >> 4, bc4 = (tid & 15) * 4;

    float acc[4][4];
#pragma unroll
    for (int i = 0; i < 4; i++)
#pragma unroll
        for (int j = 0; j < 4; j++) acc[i][j] = 0.f;

    for (int k0 = 0; k0 < K; k0 += 16) {
        float4 a = make_float4(0.f, 0.f, 0.f, 0.f);
        if (row0 + arow < M)
            a = *reinterpret_cast<const float4*>(A + (size_t)(row0 + arow) * K + k0 + ak4);
        As[ak4 + 0][arow] = a.x; As[ak4 + 1][arow] = a.y;
        As[ak4 + 2][arow] = a.z; As[ak4 + 3][arow] = a.w;
        float4 b = make_float4(0.f, 0.f, 0.f, 0.f);
        if (col0 + bc4 < N)
            b = *reinterpret_cast<const float4*>(B + (size_t)(k0 + brow) * N + col0 + bc4);
        *reinterpret_cast<float4*>(&Bs[brow][bc4]) = b;
        __syncthreads();
#pragma unroll
        for (int kk = 0; kk < 16; kk++) {
            float4 ra = *reinterpret_cast<const float4*>(&As[kk][ty * 4]);
            float4 rb = *reinterpret_cast<const float4*>(&Bs[kk][tx * 4]);
            float av[4] = {ra.x, ra.y, ra.z, ra.w};
            float bv[4] = {rb.x, rb.y, rb.z, rb.w};
#pragma unroll
            for (int i = 0; i < 4; i++)
#pragma unroll
                for (int j = 0; j < 4; j++) acc[i][j] += av[i] * bv[j];
        }
        __syncthreads();
    }
    int c0 = col0 + tx * 4;
    if (c0 < N) {
        float4 bv = *reinterpret_cast<const float4*>(bias + c0);
#pragma unroll
        for (int i = 0; i < 4; i++) {
            int r = row0 + ty * 4 + i;
            if (r < M) {
                float4 o;
                o.x = acc[i][0] + bv.x; o.y = acc[i][1] + bv.y;
                o.z = acc[i][2] + bv.z; o.w = acc[i][3] + bv.w;
                *reinterpret_cast<float4*>(C + (size_t)r * N + c0) = o;
            }
        }
    }
}

// ---------------- host orchestration ----------------
extern "C" void kernel_launch(void* const* d_in, const int* in_sizes, int n_in,
                              void* d_out, int out_size) {
    const float* feat  = (const float*)d_in[0];
    const int*   src   = (const int*)d_in[1];
    const int*   dst   = (const int*)d_in[2];
    const float* W_fc  = (const float*)d_in[3];
    const float* b_fc  = (const float*)d_in[4];
    const float* W1    = (const float*)d_in[5];
    const float* b1    = (const float*)d_in[6];
    const float* W2    = (const float*)d_in[7];
    const float* b2    = (const float*)d_in[8];
    const float* W3    = (const float*)d_in[9];
    const float* b3    = (const float*)d_in[10];
    const float* gamma = (const float*)d_in[11];
    const float* beta  = (const float*)d_in[12];
    const float* W_lin = (const float*)d_in[13];
    const float* b_lin = (const float*)d_in[14];

    const int Nn = in_sizes[0] / FDIM;      // 50000
    const int E = in_sizes[1];              // 300000
    const int C = in_sizes[13] / DDIM;      // 40

    float* out_x = (float*)d_out;
    float* out_logits = out_x + (size_t)Nn * DDIM;

    float *px, *pm, *pns, *pnd, *psum, *psumsq;
    __nv_bfloat16 *pbthi, *pbtlo;
    cudaGetSymbolAddress((void**)&px, g_x);
    cudaGetSymbolAddress((void**)&pm, g_m);
    cudaGetSymbolAddress((void**)&pns, g_ns);
    cudaGetSymbolAddress((void**)&pnd, g_nd);
    cudaGetSymbolAddress((void**)&psum, g_sum);
    cudaGetSymbolAddress((void**)&psumsq, g_sumsq);
    cudaGetSymbolAddress((void**)&pbthi, g_bthi);
    cudaGetSymbolAddress((void**)&pbtlo, g_btlo);

    cudaFuncSetAttribute(gemm_mma_kernel, cudaFuncAttributeMaxDynamicSharedMemorySize, MMA_SMEM);

    const int nd4 = (Nn * DDIM) / 4;
    const int elems = Nn * DDIM;
    dim3 ggrid(2, (Nn + 127) / 128);        // 2 col-blocks x 391 row-blocks

    // --- degree norms ---
    zero_kernel<<<(Nn / 4 + 255) / 256, 256>>>(pns, Nn / 4);
    zero_kernel<<<(Nn / 4 + 255) / 256, 256>>>(pnd, Nn / 4);
    degree_kernel<<<(E + 255) / 256, 256>>>(src, dst, pns, pnd, E);
    norm_fin_kernel<<<(Nn + 255) / 256, 256>>>(pns, pnd, Nn);

    // --- x = feat @ W_fc + b_fc (fused-convert bf16 split MMA, K=1024) ---
    split_w_kernel<<<(DDIM * FDIM + 255) / 256, 256>>>(W_fc, pbthi, pbtlo, FDIM, DDIM, 10);
    gemm_mma_kernel<<<ggrid, 256, MMA_SMEM>>>(feat, nullptr, pbthi, pbtlo, b_fc, px, Nn, FDIM);

    // --- layer 1 ---
    zero_kernel<<<(nd4 + 255) / 256, 256>>>(pm, nd4);
    scatter_kernel<<<(E * 32 + 255) / 256, 256>>>(px, pns, src, dst, pm, E);
    split_w_kernel<<<(DDIM * DDIM + 255) / 256, 256>>>(W1, pbthi, pbtlo, DDIM, DDIM, 8);
    gemm_mma_kernel<<<ggrid, 256, MMA_SMEM>>>(pm, pnd, pbthi, pbtlo, b1, px, Nn, DDIM);
    zero_kernel<<<1, 128>>>(psum, DDIM / 4);
    zero_kernel<<<1, 128>>>(psumsq, DDIM / 4);
    bn_stats_kernel<<<512, DDIM>>>(px, psum, psumsq, Nn);
    bn_elu_kernel<<<(elems + 255) / 256, 256>>>(px, psum, psumsq, gamma, beta, Nn);

    // --- layer 2 ---
    zero_kernel<<<(nd4 + 255) / 256, 256>>>(pm, nd4);
    scatter_kernel<<<(E * 32 + 255) / 256, 256>>>(px, pns, src, dst, pm, E);
    split_w_kernel<<<(DDIM * DDIM + 255) / 256, 256>>>(W2, pbthi, pbtlo, DDIM, DDIM, 8);
    gemm_mma_kernel<<<ggrid, 256, MMA_SMEM>>>(pm, pnd, pbthi, pbtlo, b2, px, Nn, DDIM);
    zero_kernel<<<1, 128>>>(psum, DDIM / 4);
    zero_kernel<<<1, 128>>>(psumsq, DDIM / 4);
    bn_stats_kernel<<<512, DDIM>>>(px, psum, psumsq, Nn);
    bn_elu_kernel<<<(elems + 255) / 256, 256>>>(px, psum, psumsq, gamma, beta, Nn);

    // --- layer 3 (output x -> d_out) ---
    zero_kernel<<<(nd4 + 255) / 256, 256>>>(pm, nd4);
    scatter_kernel<<<(E * 32 + 255) / 256, 256>>>(px, pns, src, dst, pm, E);
    split_w_kernel<<<(DDIM * DDIM + 255) / 256, 256>>>(W3, pbthi, pbtlo, DDIM, DDIM, 8);
    gemm_mma_kernel<<<ggrid, 256, MMA_SMEM>>>(pm, pnd, pbthi, pbtlo, b3, out_x, Nn, DDIM);

    // --- logits = x @ W_lin + b_lin (SIMT, N=40) ---
    gemm_simt_kernel<<<dim3((C + 63) / 64, (Nn + 63) / 64), 256>>>(out_x, W_lin, b_lin,
                                                                   out_logits, Nn, C, DDIM);
}